// round 3
// baseline (speedup 1.0000x reference)
#include <cuda_runtime.h>
#include <cuda_bf16.h>
#include <math.h>

#define B_   2
#define S_   2048
#define HID  2048
#define NH   16
#define HD   128
#define RK   64
#define BS_ROWS (B_*S_)        // 4096
#define HROWS   (B_*S_*NH)     // 65536

// -------- scratch (static __device__; no allocation allowed) --------
__device__ float g_Q[BS_ROWS*HID];
__device__ float g_K[BS_ROWS*HID];
__device__ float g_V[BS_ROWS*HID];
__device__ float g_qa[HROWS*RK];
__device__ float g_kc[HROWS*RK];
__device__ float g_vc[HROWS*RK];
__device__ float g_qg[HROWS*HD];
__device__ float g_oc[HROWS*RK];
__device__ float g_gated[BS_ROWS*HID];

// =====================================================================
// SGEMM: C[M,N] = A[M,K] @ B[K,N], fp32, all dims multiples of 128
// 128x128 block tile, BK=8, 256 threads, 8x8 microtile per thread.
// =====================================================================
__global__ __launch_bounds__(256) void sgemm128(
    const float* __restrict__ A, const float* __restrict__ Bm,
    float* __restrict__ C, int M, int N, int K)
{
    __shared__ float As[8][128];
    __shared__ float Bs[8][128];

    const int tid  = threadIdx.x;
    const int tx   = tid & 15;
    const int ty   = tid >> 4;
    const int row0 = blockIdx.y * 128;
    const int col0 = blockIdx.x * 128;

    const int aRow = tid >> 1;          // 0..127
    const int aCol = (tid & 1) << 2;    // 0 or 4
    const int bRow = tid >> 5;          // 0..7
    const int bCol = (tid & 31) << 2;   // 0..124

    const float* Ap = A  + (size_t)(row0 + aRow) * K + aCol;
    const float* Bp = Bm + (size_t)bRow * N + col0 + bCol;

    float acc[8][8];
#pragma unroll
    for (int i = 0; i < 8; i++)
#pragma unroll
        for (int j = 0; j < 8; j++) acc[i][j] = 0.f;

    for (int kt = 0; kt < K; kt += 8) {
        float4 a4 = *(const float4*)(Ap + kt);
        float4 b4 = *(const float4*)(Bp + (size_t)kt * N);
        As[aCol + 0][aRow] = a4.x;
        As[aCol + 1][aRow] = a4.y;
        As[aCol + 2][aRow] = a4.z;
        As[aCol + 3][aRow] = a4.w;
        *(float4*)&Bs[bRow][bCol] = b4;
        __syncthreads();

#pragma unroll
        for (int k = 0; k < 8; k++) {
            float ar[8], br[8];
#pragma unroll
            for (int i = 0; i < 4; i++) {
                float4 t = *(const float4*)&As[k][ty * 8 + i * 4];
                ar[i*4+0]=t.x; ar[i*4+1]=t.y; ar[i*4+2]=t.z; ar[i*4+3]=t.w;
                (void)0;
            }
#pragma unroll
            for (int j = 0; j < 2; j++) {
                float4 t = *(const float4*)&Bs[k][tx * 8 + j * 4];
                br[j*4+0]=t.x; br[j*4+1]=t.y; br[j*4+2]=t.z; br[j*4+3]=t.w;
            }
#pragma unroll
            for (int i = 0; i < 8; i++)
#pragma unroll
                for (int j = 0; j < 8; j++)
                    acc[i][j] += ar[i] * br[j];
        }
        __syncthreads();
    }

#pragma unroll
    for (int i = 0; i < 8; i++) {
        float* cp = C + (size_t)(row0 + ty * 8 + i) * N + col0 + tx * 8;
        float4 o0 = make_float4(acc[i][0], acc[i][1], acc[i][2], acc[i][3]);
        float4 o1 = make_float4(acc[i][4], acc[i][5], acc[i][6], acc[i][7]);
        *(float4*)cp       = o0;
        *(float4*)(cp + 4) = o1;
    }
}

// =====================================================================
// RoPE + per-head projections.
// One warp per head-row (b,s,h). 8 rows / block.
//   qa = rope(q) @ Wqa[128,64]; kc = rope(k) @ Wkc; vc = v @ Wvc;
//   qg = rope(q) @ Wqg[128,128]
// =====================================================================
__global__ __launch_bounds__(256) void rope_proj(
    const int*   __restrict__ pos_ids,
    const float* __restrict__ Wqa, const float* __restrict__ Wkc,
    const float* __restrict__ Wvc, const float* __restrict__ Wqg)
{
    __shared__ float sQ[8][128], sK[8][128], sV[8][128];
    const int warp = threadIdx.x >> 5;
    const int lane = threadIdx.x & 31;
    const int row  = blockIdx.x * 8 + warp;       // (b*S+s)*NH + h
    const int bs   = row >> 4;
    const int h    = row & 15;
    const int s    = bs & (S_ - 1);

    const size_t hoff = (size_t)bs * HID + h * HD;
    *(float4*)&sQ[warp][lane * 4] = *(const float4*)(g_Q + hoff + lane * 4);
    *(float4*)&sK[warp][lane * 4] = *(const float4*)(g_K + hoff + lane * 4);
    *(float4*)&sV[warp][lane * 4] = *(const float4*)(g_V + hoff + lane * 4);
    __syncwarp();

    // RoPE on dims [0,64): out[i]=x1*c - x2*s ; out[i+32]=x2*c + x1*s
    const float pos  = (float)pos_ids[s];
    const float invf = 1.0f / powf(10000.0f, (float)(2 * lane) * (1.0f / 64.0f));
    const float ang  = pos * invf;
    const float c = cosf(ang), sn = sinf(ang);
    {
        float x1 = sQ[warp][lane], x2 = sQ[warp][lane + 32];
        sQ[warp][lane]      = x1 * c - x2 * sn;
        sQ[warp][lane + 32] = x2 * c + x1 * sn;
        x1 = sK[warp][lane]; x2 = sK[warp][lane + 32];
        sK[warp][lane]      = x1 * c - x2 * sn;
        sK[warp][lane + 32] = x2 * c + x1 * sn;
    }
    __syncwarp();

    float a0=0,a1=0,b0=0,b1=0,c0=0,c1=0,g0=0,g1=0,g2=0,g3=0;
#pragma unroll 4
    for (int d = 0; d < 128; d++) {
        const float xq = sQ[warp][d];
        const float xk = sK[warp][d];
        const float xv = sV[warp][d];
        a0 += xq * __ldg(&Wqa[d * 64  + lane]);
        a1 += xq * __ldg(&Wqa[d * 64  + lane + 32]);
        b0 += xk * __ldg(&Wkc[d * 64  + lane]);
        b1 += xk * __ldg(&Wkc[d * 64  + lane + 32]);
        c0 += xv * __ldg(&Wvc[d * 64  + lane]);
        c1 += xv * __ldg(&Wvc[d * 64  + lane + 32]);
        g0 += xq * __ldg(&Wqg[d * 128 + lane]);
        g1 += xq * __ldg(&Wqg[d * 128 + lane + 32]);
        g2 += xq * __ldg(&Wqg[d * 128 + lane + 64]);
        g3 += xq * __ldg(&Wqg[d * 128 + lane + 96]);
    }
    g_qa[(size_t)row * 64 + lane]       = a0;
    g_qa[(size_t)row * 64 + lane + 32]  = a1;
    g_kc[(size_t)row * 64 + lane]       = b0;
    g_kc[(size_t)row * 64 + lane + 32]  = b1;
    g_vc[(size_t)row * 64 + lane]       = c0;
    g_vc[(size_t)row * 64 + lane + 32]  = c1;
    g_qg[(size_t)row * 128 + lane]      = g0;
    g_qg[(size_t)row * 128 + lane + 32] = g1;
    g_qg[(size_t)row * 128 + lane + 64] = g2;
    g_qg[(size_t)row * 128 + lane + 96] = g3;
}

// =====================================================================
// Flash attention, fp32: per (b,h): softmax(qa kc^T / 8) @ vc
// Q-tile 64 rows, K-tile 64. 256 threads, 4x4 microtile per thread.
// =====================================================================
#define AP 68  // row pad: 16B-aligned rows, low smem bank conflict
__global__ __launch_bounds__(256) void attn_kernel()
{
    extern __shared__ float sm[];
    float (*Qs)[AP] = (float(*)[AP])(sm);
    float (*Ks)[AP] = (float(*)[AP])(sm + 64 * AP);
    float (*Vs)[AP] = (float(*)[AP])(sm + 2 * 64 * AP);
    float (*Ps)[AP] = (float(*)[AP])(sm + 3 * 64 * AP);
    float* mrow = sm + 4 * 64 * AP;
    float* lrow = mrow + 64;
    float* arow = lrow + 64;

    const int tid = threadIdx.x;
    const int tx  = tid & 15;
    const int ty  = tid >> 4;
    const int b   = blockIdx.y >> 4;
    const int h   = blockIdx.y & 15;
    const int q0  = blockIdx.x * 64;
    const int i0  = ty * 4, j0 = tx * 4;

    for (int idx = tid; idx < 64 * 16; idx += 256) {
        const int r = idx >> 4, c4 = (idx & 15) << 2;
        *(float4*)&Qs[r][c4] =
            *(const float4*)(g_qa + ((size_t)(b * S_ + q0 + r) * NH + h) * RK + c4);
    }
    if (tid < 64) { mrow[tid] = -INFINITY; lrow[tid] = 0.f; }

    float acc[4][4];
#pragma unroll
    for (int i = 0; i < 4; i++)
#pragma unroll
        for (int j = 0; j < 4; j++) acc[i][j] = 0.f;

    for (int kt = 0; kt < S_; kt += 64) {
        __syncthreads();  // previous tile's consumers done; Qs/stat init visible
        for (int idx = tid; idx < 64 * 16; idx += 256) {
            const int r = idx >> 4, c4 = (idx & 15) << 2;
            const size_t base = ((size_t)(b * S_ + kt + r) * NH + h) * RK + c4;
            *(float4*)&Ks[r][c4] = *(const float4*)(g_kc + base);
            *(float4*)&Vs[r][c4] = *(const float4*)(g_vc + base);
        }
        __syncthreads();

        // S = Q K^T  (64x64x64)
        float s[4][4];
#pragma unroll
        for (int i = 0; i < 4; i++)
#pragma unroll
            for (int j = 0; j < 4; j++) s[i][j] = 0.f;

#pragma unroll 4
        for (int r = 0; r < 64; r += 4) {
            float4 aa[4], bb[4];
#pragma unroll
            for (int ii = 0; ii < 4; ii++) aa[ii] = *(const float4*)&Qs[i0 + ii][r];
#pragma unroll
            for (int jj = 0; jj < 4; jj++) bb[jj] = *(const float4*)&Ks[j0 + jj][r];
#pragma unroll
            for (int ii = 0; ii < 4; ii++)
#pragma unroll
                for (int jj = 0; jj < 4; jj++)
                    s[ii][jj] += aa[ii].x * bb[jj].x + aa[ii].y * bb[jj].y
                               + aa[ii].z * bb[jj].z + aa[ii].w * bb[jj].w;
        }
#pragma unroll
        for (int ii = 0; ii < 4; ii++)
#pragma unroll
            for (int jj = 0; jj < 4; jj++)
                Ps[i0 + ii][j0 + jj] = s[ii][jj] * 0.125f;
        __syncthreads();

        // Online softmax row stats: one thread per row
        if (tid < 64) {
            const int r = tid;
            float m_old = mrow[r];
            float mt = m_old;
#pragma unroll 8
            for (int j = 0; j < 64; j++) mt = fmaxf(mt, Ps[r][j]);
            const float alpha = expf(m_old - mt);
            float sum = 0.f;
#pragma unroll 8
            for (int j = 0; j < 64; j++) {
                const float p = expf(Ps[r][j] - mt);
                Ps[r][j] = p;
                sum += p;
            }
            lrow[r] = lrow[r] * alpha + sum;
            mrow[r] = mt;
            arow[r] = alpha;
        }
        __syncthreads();

        float al[4];
#pragma unroll
        for (int ii = 0; ii < 4; ii++) al[ii] = arow[i0 + ii];
#pragma unroll
        for (int ii = 0; ii < 4; ii++)
#pragma unroll
            for (int jj = 0; jj < 4; jj++) acc[ii][jj] *= al[ii];

        // O += P @ V  (64x64x64)
#pragma unroll 4
        for (int r = 0; r < 64; r += 4) {
            float4 pp[4], vv[4];
#pragma unroll
            for (int ii = 0; ii < 4; ii++) pp[ii] = *(const float4*)&Ps[i0 + ii][r];
#pragma unroll
            for (int rr = 0; rr < 4; rr++) vv[rr] = *(const float4*)&Vs[r + rr][j0];
#pragma unroll
            for (int ii = 0; ii < 4; ii++) {
                acc[ii][0] += pp[ii].x*vv[0].x + pp[ii].y*vv[1].x + pp[ii].z*vv[2].x + pp[ii].w*vv[3].x;
                acc[ii][1] += pp[ii].x*vv[0].y + pp[ii].y*vv[1].y + pp[ii].z*vv[2].y + pp[ii].w*vv[3].y;
                acc[ii][2] += pp[ii].x*vv[0].z + pp[ii].y*vv[1].z + pp[ii].z*vv[2].z + pp[ii].w*vv[3].z;
                acc[ii][3] += pp[ii].x*vv[0].w + pp[ii].y*vv[1].w + pp[ii].z*vv[2].w + pp[ii].w*vv[3].w;
            }
        }
    }

#pragma unroll
    for (int ii = 0; ii < 4; ii++) {
        const float inv_l = 1.0f / lrow[i0 + ii];
        float* op = g_oc + ((size_t)(b * S_ + q0 + i0 + ii) * NH + h) * RK + j0;
#pragma unroll
        for (int jj = 0; jj < 4; jj++) op[jj] = acc[ii][jj] * inv_l;
    }
}

// =====================================================================
// uplift = out_c @ Wov[64,128]; gated = silu(qg) * uplift
// One warp per head-row.
// =====================================================================
__global__ __launch_bounds__(256) void uplift_gate(const float* __restrict__ Wov)
{
    __shared__ float xs[8][64];
    const int warp = threadIdx.x >> 5;
    const int lane = threadIdx.x & 31;
    const int row  = blockIdx.x * 8 + warp;     // (b*S+s)*NH + h

    *(float2*)&xs[warp][lane * 2] =
        *(const float2*)(g_oc + (size_t)row * 64 + lane * 2);
    __syncwarp();

    float acc[4] = {0.f, 0.f, 0.f, 0.f};
#pragma unroll 4
    for (int r = 0; r < 64; r++) {
        const float x = xs[warp][r];
        acc[0] += x * __ldg(&Wov[r * 128 + lane]);
        acc[1] += x * __ldg(&Wov[r * 128 + lane + 32]);
        acc[2] += x * __ldg(&Wov[r * 128 + lane + 64]);
        acc[3] += x * __ldg(&Wov[r * 128 + lane + 96]);
    }
    const int bs = row >> 4, h = row & 15;
    float* gp = g_gated + (size_t)bs * HID + h * HD;
#pragma unroll
    for (int k = 0; k < 4; k++) {
        const float g   = g_qg[(size_t)row * 128 + lane + 32 * k];
        const float sil = g / (1.0f + expf(-g));
        gp[lane + 32 * k] = sil * acc[k];
    }
}

// =====================================================================
extern "C" void kernel_launch(void* const* d_in, const int* in_sizes, int n_in,
                              void* d_out, int out_size)
{
    const float* hs  = (const float*)d_in[0];
    const int*   pos = (const int*)  d_in[1];
    const float* Wq  = (const float*)d_in[2];
    const float* Wk  = (const float*)d_in[3];
    const float* Wv  = (const float*)d_in[4];
    const float* Wkc = (const float*)d_in[5];
    const float* Wvc = (const float*)d_in[6];
    const float* Wqa = (const float*)d_in[7];
    const float* Wqg = (const float*)d_in[8];
    const float* Wov = (const float*)d_in[9];
    const float* Wo  = (const float*)d_in[10];
    float* out = (float*)d_out;

    float *pQ, *pK, *pV, *pG;
    cudaGetSymbolAddress((void**)&pQ, g_Q);
    cudaGetSymbolAddress((void**)&pK, g_K);
    cudaGetSymbolAddress((void**)&pV, g_V);
    cudaGetSymbolAddress((void**)&pG, g_gated);

    const dim3 gg(HID / 128, BS_ROWS / 128);
    sgemm128<<<gg, 256>>>(hs, Wq, pQ, BS_ROWS, HID, HID);
    sgemm128<<<gg, 256>>>(hs, Wk, pK, BS_ROWS, HID, HID);
    sgemm128<<<gg, 256>>>(hs, Wv, pV, BS_ROWS, HID, HID);

    rope_proj<<<HROWS / 8, 256>>>(pos, Wqa, Wkc, Wvc, Wqg);

    const int att_smem = (4 * 64 * AP + 192) * (int)sizeof(float);
    cudaFuncSetAttribute(attn_kernel,
                         cudaFuncAttributeMaxDynamicSharedMemorySize, att_smem);
    attn_kernel<<<dim3(S_ / 64, B_ * NH), 256, att_smem>>>();

    uplift_gate<<<HROWS / 8, 256>>>(Wov);

    sgemm128<<<gg, 256>>>(pG, Wo, out, BS_ROWS, HID, HID);
}